// round 6
// baseline (speedup 1.0000x reference)
#include <cuda_runtime.h>

#define GS     16
#define NPAIR  136          // 16*17/2 lower-triangular pairs
#define NACC   152          // 136 pair sums + 16 channel sums
#define GROUPS 32
#define BATCH  32
#define HW     3136         // 56*56
#define HW4    784          // HW/4 (float4 units)
#define CH     512
#define CHUNK  32           // float4 positions staged per chunk
#define NCHUNK 25           // ceil(784/32)

typedef unsigned long long ull;

static __device__ float d_acc[GROUPS][NACC];   // pair sums + channel sums
static __device__ float d_Linv[GROUPS][NPAIR]; // packed lower-triangular Linv
static __device__ float d_bias[CH];            // Linv @ mean, per channel

// ---- packed f32x2 helpers (Blackwell) --------------------------------------
__device__ __forceinline__ void fma2(ull& d, ull a, ull b) {
    asm("fma.rn.f32x2 %0, %1, %2, %0;" : "+l"(d) : "l"(a), "l"(b));
}
__device__ __forceinline__ void add2(ull& d, ull a) {
    asm("add.rn.f32x2 %0, %0, %1;" : "+l"(d) : "l"(a));
}
__device__ __forceinline__ float unpack_add(ull v) {
    float lo, hi;
    asm("mov.b64 {%0,%1}, %2;" : "=f"(lo), "=f"(hi) : "l"(v));
    return lo + hi;
}

// ---------------------------------------------------------------------------
__global__ void zero_kernel() {
    int i = blockIdx.x * blockDim.x + threadIdx.x;
    if (i < GROUPS * NACC) ((float*)d_acc)[i] = 0.f;
}

// ---------------------------------------------------------------------------
// Stats v4: smem-staged. Each gmem float4 read exactly once per tile.
// 320 threads. Per chunk: stage CHUNK positions x 16 channels into smem,
// then 10 warps compute pair-blocks reading ulonglong2 (packed f32x2 pairs)
// directly from smem -- no packing MOVs, no gmem re-reads.
//   warps 0-3 : diagonal quad q (10 pairs + 4 channel sums), lanes = positions
//   warps 4-9 : quad-cross blocks (16 pairs), lanes = positions
__global__ void __launch_bounds__(320, 2) stats_kernel(const float* __restrict__ x) {
    const int g = blockIdx.x & 31;
    const int b = blockIdx.x >> 5;
    const float4* in = (const float4*)(x + ((size_t)b * CH + (size_t)g * GS) * HW);

    __shared__ float4 buf[GS][CHUNK];   // 8 KB

    const int tid  = threadIdx.x;
    const int wid  = tid >> 5;
    const int lane = tid & 31;

    // cross-role quad pair table (qi > qj)
    const int QI[6] = {1, 2, 3, 2, 3, 3};
    const int QJ[6] = {0, 0, 0, 1, 1, 2};
    const int qi = (wid >= 4) ? QI[wid - 4] : wid;   // diag: quad = wid
    const int qj = (wid >= 4) ? QJ[wid - 4] : wid;

    // staging slots: idx = tid, tid+320 (512 float4 per chunk)
    const int c0 = tid >> 5;            // wait -- idx layout: c = idx/CHUNK
    (void)c0;

    ull acc[16];
#pragma unroll
    for (int k = 0; k < 16; k++) acc[k] = 0ull;

    // prefetch chunk 0
    float4 st0, st1;
    {
        const int i0 = tid, i1 = tid + 320;
        const int ch0 = i0 >> 5, p0 = i0 & 31;
        st0 = (p0 < HW4) ? __ldg(in + (size_t)ch0 * HW4 + p0)
                         : make_float4(0.f, 0.f, 0.f, 0.f);
        if (i1 < GS * CHUNK) {
            const int ch1 = i1 >> 5, p1 = i1 & 31;
            st1 = (p1 < HW4) ? __ldg(in + (size_t)ch1 * HW4 + p1)
                             : make_float4(0.f, 0.f, 0.f, 0.f);
        }
    }

    for (int k = 0; k < NCHUNK; k++) {
        // store staged regs into smem
        {
            const int i0 = tid, i1 = tid + 320;
            buf[i0 >> 5][i0 & 31] = st0;
            if (i1 < GS * CHUNK) buf[i1 >> 5][i1 & 31] = st1;
        }
        // issue next chunk's loads (overlap with compute below)
        if (k + 1 < NCHUNK) {
            const int base = (k + 1) * CHUNK;
            const int i0 = tid, i1 = tid + 320;
            const int ch0 = i0 >> 5, p0 = base + (i0 & 31);
            st0 = (p0 < HW4) ? __ldg(in + (size_t)ch0 * HW4 + p0)
                             : make_float4(0.f, 0.f, 0.f, 0.f);
            if (i1 < GS * CHUNK) {
                const int ch1 = i1 >> 5, p1 = base + (i1 & 31);
                st1 = (p1 < HW4) ? __ldg(in + (size_t)ch1 * HW4 + p1)
                                 : make_float4(0.f, 0.f, 0.f, 0.f);
            }
        }
        __syncthreads();

        if (wid < 4) {
            // diagonal quad: 10 pairs (acc[0..9]) + 4 sums (acc[10..13])
            ulonglong2 v[4];
#pragma unroll
            for (int c = 0; c < 4; c++)
                v[c] = *(const ulonglong2*)&buf[qi * 4 + c][lane];
#pragma unroll
            for (int i = 0; i < 4; i++) {
#pragma unroll
                for (int j = 0; j <= i; j++) {
                    const int kk = i * (i + 1) / 2 + j;
                    fma2(acc[kk], v[i].x, v[j].x);
                    fma2(acc[kk], v[i].y, v[j].y);
                }
                add2(acc[10 + i], v[i].x);
                add2(acc[10 + i], v[i].y);
            }
        } else {
            // cross block: 16 pairs, i in quad qi, j in quad qj
            ulonglong2 u[4], w[4];
#pragma unroll
            for (int c = 0; c < 4; c++) {
                u[c] = *(const ulonglong2*)&buf[qi * 4 + c][lane];
                w[c] = *(const ulonglong2*)&buf[qj * 4 + c][lane];
            }
#pragma unroll
            for (int i = 0; i < 4; i++)
#pragma unroll
                for (int j = 0; j < 4; j++) {
                    const int kk = i * 4 + j;
                    fma2(acc[kk], u[i].x, w[j].x);
                    fma2(acc[kk], u[i].y, w[j].y);
                }
        }
        __syncthreads();
    }

    // reduce + emit
    float r[16];
#pragma unroll
    for (int k = 0; k < 16; k++) r[k] = unpack_add(acc[k]);
#pragma unroll
    for (int k = 0; k < 16; k++) {
#pragma unroll
        for (int off = 16; off > 0; off >>= 1)
            r[k] += __shfl_xor_sync(0xffffffffu, r[k], off);
    }
    if (lane == 0) {
        if (wid < 4) {
            for (int i = 0; i < 4; i++) {
                for (int j = 0; j <= i; j++) {
                    const int gi = qi * 4 + i, gj = qi * 4 + j;
                    atomicAdd(&d_acc[g][gi * (gi + 1) / 2 + gj], r[i * (i + 1) / 2 + j]);
                }
                atomicAdd(&d_acc[g][NPAIR + qi * 4 + i], r[10 + i]);
            }
        } else {
            for (int i = 0; i < 4; i++)
                for (int j = 0; j < 4; j++) {
                    const int gi = qi * 4 + i, gj = qj * 4 + j;
                    atomicAdd(&d_acc[g][gi * (gi + 1) / 2 + gj], r[i * 4 + j]);
                }
        }
    }
}

// ---------------------------------------------------------------------------
// Solve: one block per group, 16 threads, everything in shared memory, fp64.
__global__ void __launch_bounds__(16) solve_kernel() {
    const int g = blockIdx.x;
    const int t = threadIdx.x;
    __shared__ double P[GS][GS + 1];
    __shared__ double L[GS][GS + 1];
    __shared__ double V[GS][GS + 1];
    __shared__ double m[GS];

    const double Nd   = (double)BATCH * (double)HW;
    const double EPSd = 1e-3;
    const unsigned MASK = 0xffffu;

    m[t] = (double)d_acc[g][NPAIR + t] / Nd;
    __syncwarp(MASK);

    for (int j = 0; j < GS; j++) {
        const int i_ = t > j ? t : j, j_ = t > j ? j : t;
        double c = (double)d_acc[g][i_ * (i_ + 1) / 2 + j_] / Nd - m[t] * m[j];
        c *= (1.0 - EPSd);
        if (t == j) c += EPSd;
        P[t][j] = c;
    }
    __syncwarp(MASK);

    for (int j = 0; j < GS; j++) {
        if (t == j) {
            double s = P[j][j];
            for (int k = 0; k < j; k++) s -= L[j][k] * L[j][k];
            L[j][j] = sqrt(s);
        }
        __syncwarp(MASK);
        if (t > j) {
            double s = P[t][j];
            for (int k = 0; k < j; k++) s -= L[t][k] * L[j][k];
            L[t][j] = s / L[j][j];
        }
        __syncwarp(MASK);
    }

    V[t][t] = 1.0 / L[t][t];
    for (int i = t + 1; i < GS; i++) {
        double s = 0.0;
        for (int k = t; k < i; k++) s += L[i][k] * V[k][t];
        V[i][t] = -s / L[i][i];
    }
    __syncwarp(MASK);

    double bsum = 0.0;
    for (int j = 0; j <= t; j++) {
        d_Linv[g][t * (t + 1) / 2 + j] = (float)V[t][j];
        bsum += V[t][j] * m[j];
    }
    d_bias[g * GS + t] = (float)bsum;
}

// ---------------------------------------------------------------------------
// Apply (unchanged, proven 66us / 68% DRAM):
// out_i = sum_{j<=i} Linv_ij * x_j - bias_i, float4, streaming stores.
__global__ void __launch_bounds__(256, 2) apply_kernel(const float* __restrict__ x,
                                                       float* __restrict__ out) {
    const int g = blockIdx.x & 31;
    const int b = blockIdx.x >> 5;

    __shared__ float Ls[NPAIR];
    __shared__ float bs[GS];
    if (threadIdx.x < NPAIR) Ls[threadIdx.x] = d_Linv[g][threadIdx.x];
    if (threadIdx.x < GS)    bs[threadIdx.x] = d_bias[g * GS + threadIdx.x];
    __syncthreads();

    const size_t off = ((size_t)b * CH + (size_t)g * GS) * HW;
    const float4* in = (const float4*)(x + off);
    float4*       op = (float4*)(out + off);

    for (int pos = threadIdx.x; pos < HW4; pos += 256) {
        float4 v[GS];
#pragma unroll
        for (int c = 0; c < GS; c++) v[c] = in[(size_t)c * HW4 + pos];
#pragma unroll
        for (int i = 0; i < GS; i++) {
            const float bias = bs[i];
            float4 a;
            a.x = -bias; a.y = -bias; a.z = -bias; a.w = -bias;
#pragma unroll
            for (int j = 0; j <= i; j++) {
                const float f = Ls[i * (i + 1) / 2 + j];
                a.x = fmaf(f, v[j].x, a.x);
                a.y = fmaf(f, v[j].y, a.y);
                a.z = fmaf(f, v[j].z, a.z);
                a.w = fmaf(f, v[j].w, a.w);
            }
            __stcs(&op[(size_t)i * HW4 + pos], a);
        }
    }
}

// ---------------------------------------------------------------------------
extern "C" void kernel_launch(void* const* d_in, const int* in_sizes, int n_in,
                              void* d_out, int out_size) {
    const float* x   = (const float*)d_in[0];
    float*       out = (float*)d_out;

    zero_kernel<<<(GROUPS * NACC + 255) / 256, 256>>>();
    stats_kernel<<<GROUPS * BATCH, 320>>>(x);
    solve_kernel<<<GROUPS, 16>>>();
    apply_kernel<<<GROUPS * BATCH, 256>>>(x, out);
}